// round 2
// baseline (speedup 1.0000x reference)
#include <cuda_runtime.h>
#include <math.h>

#define Bsz 4
#define Dd  96
#define Hh  64
#define Ww  64
#define Ll  4096
#define Kk  4
#define Nn  16
#define Rr  6
#define C38 38
#define NCk 64   // number of chunks
#define LCk 64   // chunk length (NCk*LCk == Ll)

// ---------------- scratch (__device__ globals; no allocations) ----------------
__device__ float g_xpf  [Bsz*Ll*Dd];           // x permuted (B,L,D), row-major spatial
__device__ float g_xpt  [Bsz*Ll*Dd];           // x permuted (B,L,D), col-major spatial
__device__ float g_delta[Bsz*Kk*Ll*Dd];        // softplus(delta) (B,K,L,D)
__device__ float g_Bsc  [Bsz*Kk*Ll*Nn];        // Bs (B,K,L,N)
__device__ float g_Csc  [Bsz*Kk*Ll*Nn];        // Cs (B,K,L,N)
__device__ float g_hc   [Bsz*Kk*NCk*Dd*Nn];    // chunk-local end states
__device__ float g_Pp   [Bsz*Kk*NCk*Dd*Nn];    // chunk decay products
__device__ float g_hin  [Bsz*Kk*NCk*Dd*Nn];    // chunk incoming states
__device__ float g_ys   [Kk*Bsz*Ll*Dd];        // per-direction y in merge-target space

__device__ __forceinline__ float ex2f(float x){
    float r; asm("ex2.approx.ftz.f32 %0, %1;" : "=f"(r) : "f"(x)); return r;
}
__device__ __forceinline__ float softplus_f(float x){
    return fmaxf(x, 0.f) + log1pf(__expf(-fabsf(x)));
}

// ---------------- kernel 1: transpose x -> (B,L,D) in both traversal orders ---
__global__ void k_transpose(const float* __restrict__ x){
    __shared__ float tile[32][33];
    int b = blockIdx.z, d0 = blockIdx.y*32, l0 = blockIdx.x*32;
    int tx = threadIdx.x, ty = threadIdx.y;     // block (32,8)
    #pragma unroll
    for (int i=0;i<4;i++){
        tile[ty+8*i][tx] = x[((long)b*Dd + d0+ty+8*i)*Ll + l0+tx];
    }
    __syncthreads();
    #pragma unroll
    for (int i=0;i<4;i++){
        int l = l0 + ty + 8*i;
        int d = d0 + tx;
        float v = tile[tx][ty+8*i];
        g_xpf[((long)b*Ll + l)*Dd + d] = v;
        int lp = ((l & 63) << 6) | (l >> 6);    // spatial transpose index
        g_xpt[((long)b*Ll + lp)*Dd + d] = v;
    }
}

// ---------------- kernel 2: projections (x_dbl split + dt proj + softplus) ----
__global__ void __launch_bounds__(128) k_proj(const float* __restrict__ xw,
                                              const float* __restrict__ dtw,
                                              const float* __restrict__ dtb){
    __shared__ float swx [2*C38*Dd];
    __shared__ float swdt[2*Dd*Rr];
    __shared__ float sbia[2*Dd];
    int o = blockIdx.y, b = blockIdx.z;
    int tid = threadIdx.x;
    for (int i=tid;i<2*C38*Dd;i+=128){
        int ki = i/(C38*Dd); int rem = i - ki*(C38*Dd);
        swx[i] = xw[(o + 2*ki)*C38*Dd + rem];
    }
    for (int i=tid;i<2*Dd*Rr;i+=128){
        int ki = i/(Dd*Rr); int rem = i - ki*(Dd*Rr);
        swdt[i] = dtw[(o + 2*ki)*Dd*Rr + rem];
    }
    for (int i=tid;i<2*Dd;i+=128){
        int ki = i/Dd; int rem = i - ki*Dd;
        sbia[i] = dtb[(o + 2*ki)*Dd + rem];
    }
    __syncthreads();

    int p = blockIdx.x*128 + tid;
    const float* xp = (o==0 ? g_xpf : g_xpt) + ((long)b*Ll + p)*Dd;
    float xv[Dd];
    #pragma unroll
    for (int i=0;i<Dd/4;i++){
        float4 v = reinterpret_cast<const float4*>(xp)[i];
        xv[4*i]=v.x; xv[4*i+1]=v.y; xv[4*i+2]=v.z; xv[4*i+3]=v.w;
    }

    for (int ki=0; ki<2; ki++){
        int k = o + 2*ki;
        int l = (ki==0) ? p : (Ll-1-p);
        const float* wk = swx + ki*C38*Dd;
        long bkl = ((long)(b*Kk + k))*Ll + l;

        // dts (first R rows)
        float dts[Rr];
        #pragma unroll
        for (int c=0;c<Rr;c++){
            float acc = 0.f;
            #pragma unroll
            for (int d=0; d<Dd; d++) acc += xv[d]*wk[c*Dd+d];
            dts[c] = acc;
        }
        // Bs rows
        for (int cc=0; cc<Nn/4; cc++){
            const float* w0 = wk + (Rr + 4*cc)*Dd;
            float a0=0,a1=0,a2=0,a3=0;
            #pragma unroll
            for (int d=0; d<Dd; d++){
                float xd = xv[d];
                a0 += xd*w0[d]; a1 += xd*w0[Dd+d];
                a2 += xd*w0[2*Dd+d]; a3 += xd*w0[3*Dd+d];
            }
            reinterpret_cast<float4*>(g_Bsc + bkl*Nn)[cc] = make_float4(a0,a1,a2,a3);
        }
        // Cs rows
        for (int cc=0; cc<Nn/4; cc++){
            const float* w0 = wk + (Rr + Nn + 4*cc)*Dd;
            float a0=0,a1=0,a2=0,a3=0;
            #pragma unroll
            for (int d=0; d<Dd; d++){
                float xd = xv[d];
                a0 += xd*w0[d]; a1 += xd*w0[Dd+d];
                a2 += xd*w0[2*Dd+d]; a3 += xd*w0[3*Dd+d];
            }
            reinterpret_cast<float4*>(g_Csc + bkl*Nn)[cc] = make_float4(a0,a1,a2,a3);
        }
        // delta = softplus(dts @ dtW + bias)
        const float* wd  = swdt + ki*Dd*Rr;
        const float* bia = sbia + ki*Dd;
        float* dout = g_delta + bkl*Dd;
        for (int dd=0; dd<Dd; dd+=4){
            float aa[4];
            #pragma unroll
            for (int q=0;q<4;q++){
                float acc = bia[dd+q];
                #pragma unroll
                for (int r=0;r<Rr;r++) acc += dts[r]*wd[(dd+q)*Rr + r];
                aa[q] = softplus_f(acc);
            }
            reinterpret_cast<float4*>(dout + dd)[0] = make_float4(aa[0],aa[1],aa[2],aa[3]);
        }
    }
}

// ---------------- kernel 3: pass A (chunk-local scan, zero init) --------------
__global__ void __launch_bounds__(Dd) k_scanA(const float* __restrict__ A_logs){
    __shared__ float4 sB[LCk*Nn/4];
    int c = blockIdx.x, k = blockIdx.y, b = blockIdx.z;
    int d = threadIdx.x;
    long bk = (long)b*Kk + k;

    const float4* gB4 = reinterpret_cast<const float4*>(g_Bsc + (bk*Ll + (long)c*LCk)*Nn);
    for (int i=d; i<LCk*Nn/4; i+=Dd) sB[i] = gB4[i];
    __syncthreads();

    float A2[Nn];
    const float* al = A_logs + (k*Dd + d)*Nn;
    #pragma unroll
    for (int n=0;n<Nn;n++) A2[n] = -__expf(al[n]) * 1.4426950408889634f;

    float h[Nn];
    #pragma unroll
    for (int n=0;n<Nn;n++) h[n] = 0.f;
    float S = 0.f;

    const float* dptr = g_delta + (bk*Ll + (long)c*LCk)*Dd + d;
    const float* xp = (k & 1) ? g_xpt : g_xpf;
    int l0 = c*LCk;
    const float* uptr; int ustr;
    if (k < 2){ uptr = xp + ((long)b*Ll + l0)*Dd + d;           ustr =  Dd; }
    else      { uptr = xp + ((long)b*Ll + (Ll-1-l0))*Dd + d;    ustr = -Dd; }

    #pragma unroll 2
    for (int j=0;j<LCk;j++){
        float dlt = dptr[j*Dd];
        float u = *uptr; uptr += ustr;
        float du = dlt*u;
        S += dlt;
        const float4* bj = sB + j*(Nn/4);
        #pragma unroll
        for (int q=0;q<Nn/4;q++){
            float4 bb = bj[q];
            h[4*q+0] = h[4*q+0]*ex2f(dlt*A2[4*q+0]) + du*bb.x;
            h[4*q+1] = h[4*q+1]*ex2f(dlt*A2[4*q+1]) + du*bb.y;
            h[4*q+2] = h[4*q+2]*ex2f(dlt*A2[4*q+2]) + du*bb.z;
            h[4*q+3] = h[4*q+3]*ex2f(dlt*A2[4*q+3]) + du*bb.w;
        }
    }
    long base = ((bk*NCk + c)*Dd + d)*Nn;
    float4* hcp = reinterpret_cast<float4*>(g_hc + base);
    float4* Ppp = reinterpret_cast<float4*>(g_Pp + base);
    #pragma unroll
    for (int q=0;q<Nn/4;q++){
        hcp[q] = make_float4(h[4*q], h[4*q+1], h[4*q+2], h[4*q+3]);
        Ppp[q] = make_float4(ex2f(A2[4*q]*S), ex2f(A2[4*q+1]*S),
                             ex2f(A2[4*q+2]*S), ex2f(A2[4*q+3]*S));
    }
}

// ---------------- kernel 4: inter-chunk scan ---------------------------------
__global__ void k_mid(){
    int g = blockIdx.x*blockDim.x + threadIdx.x;   // B*K*D*N threads
    if (g >= Bsz*Kk*Dd*Nn) return;
    int n  = g & (Nn-1);
    int d  = (g >> 4) % Dd;
    int bk = g / (Dd*Nn);
    float hin = 0.f;
    for (int c=0;c<NCk;c++){
        long idx = (((long)bk*NCk + c)*Dd + d)*Nn + n;
        g_hin[idx] = hin;
        hin = hin*g_Pp[idx] + g_hc[idx];
    }
}

// ---------------- kernel 5: pass B (replay with correct h_in, emit y) --------
__global__ void __launch_bounds__(Dd) k_scanB(const float* __restrict__ A_logs,
                                              const float* __restrict__ Ds){
    __shared__ float4 sB[LCk*Nn/4];
    __shared__ float4 sC[LCk*Nn/4];
    int c = blockIdx.x, k = blockIdx.y, b = blockIdx.z;
    int d = threadIdx.x;
    long bk = (long)b*Kk + k;

    const float4* gB4 = reinterpret_cast<const float4*>(g_Bsc + (bk*Ll + (long)c*LCk)*Nn);
    const float4* gC4 = reinterpret_cast<const float4*>(g_Csc + (bk*Ll + (long)c*LCk)*Nn);
    for (int i=d; i<LCk*Nn/4; i+=Dd){ sB[i] = gB4[i]; sC[i] = gC4[i]; }
    __syncthreads();

    float A2[Nn];
    const float* al = A_logs + (k*Dd + d)*Nn;
    #pragma unroll
    for (int n=0;n<Nn;n++) A2[n] = -__expf(al[n]) * 1.4426950408889634f;

    float h[Nn];
    long base = ((bk*NCk + c)*Dd + d)*Nn;
    #pragma unroll
    for (int q=0;q<Nn/4;q++){
        float4 v = reinterpret_cast<const float4*>(g_hin + base)[q];
        h[4*q]=v.x; h[4*q+1]=v.y; h[4*q+2]=v.z; h[4*q+3]=v.w;
    }
    float Dskip = Ds[k*Dd + d];

    const float* dptr = g_delta + (bk*Ll + (long)c*LCk)*Dd + d;
    const float* xp = (k & 1) ? g_xpt : g_xpf;
    int l0 = c*LCk;
    const float* uptr; int ustr;
    if (k < 2){ uptr = xp + ((long)b*Ll + l0)*Dd + d;        ustr =  Dd; }
    else      { uptr = xp + ((long)b*Ll + (Ll-1-l0))*Dd + d; ustr = -Dd; }

    float* yout = g_ys + ((long)k*Bsz + b)*Ll*Dd + d;

    #pragma unroll 2
    for (int j=0;j<LCk;j++){
        float dlt = dptr[j*Dd];
        float u = *uptr; uptr += ustr;
        float du = dlt*u;
        float y = Dskip*u;
        const float4* bj = sB + j*(Nn/4);
        const float4* cj = sC + j*(Nn/4);
        #pragma unroll
        for (int q=0;q<Nn/4;q++){
            float4 bb = bj[q];
            float4 cc = cj[q];
            h[4*q+0] = h[4*q+0]*ex2f(dlt*A2[4*q+0]) + du*bb.x;  y += h[4*q+0]*cc.x;
            h[4*q+1] = h[4*q+1]*ex2f(dlt*A2[4*q+1]) + du*bb.y;  y += h[4*q+1]*cc.y;
            h[4*q+2] = h[4*q+2]*ex2f(dlt*A2[4*q+2]) + du*bb.z;  y += h[4*q+2]*cc.z;
            h[4*q+3] = h[4*q+3]*ex2f(dlt*A2[4*q+3]) + du*bb.w;  y += h[4*q+3]*cc.w;
        }
        int l = l0 + j;
        int t;
        if (k == 0)      t = l;
        else if (k == 1) t = ((l & 63) << 6) | (l >> 6);
        else if (k == 2) t = Ll-1-l;
        else { int q2 = Ll-1-l; t = ((q2 & 63) << 6) | (q2 >> 6); }
        yout[(long)t*Dd] = y;
    }
}

// ---------------- kernel 6: 4-way merge + LayerNorm --------------------------
__global__ void __launch_bounds__(256) k_merge(const float* __restrict__ lnw,
                                               const float* __restrict__ lnb,
                                               float* __restrict__ out){
    const long BLD = (long)Bsz*Ll*Dd;
    int warp = threadIdx.x >> 5, lane = threadIdx.x & 31;
    int pos = blockIdx.x*8 + warp;
    int b = pos >> 12;              // Ll = 4096
    int l = pos & (Ll-1);
    long base = ((long)b*Ll + l)*Dd;
    float s[3]; float sum = 0.f, sq = 0.f;
    #pragma unroll
    for (int i=0;i<3;i++){
        long off = base + lane + 32*i;
        float v = g_ys[off] + g_ys[off + BLD] + g_ys[off + 2*BLD] + g_ys[off + 3*BLD];
        s[i] = v; sum += v; sq += v*v;
    }
    #pragma unroll
    for (int o2=16;o2>0;o2>>=1){
        sum += __shfl_xor_sync(0xffffffffu, sum, o2);
        sq  += __shfl_xor_sync(0xffffffffu, sq,  o2);
    }
    float mean = sum * (1.f/Dd);
    float var  = sq  * (1.f/Dd) - mean*mean;
    float inv  = rsqrtf(var + 1e-5f);
    #pragma unroll
    for (int i=0;i<3;i++){
        int dch = lane + 32*i;
        out[base + dch] = (s[i]-mean)*inv*lnw[dch] + lnb[dch];
    }
}

// ---------------- launch ------------------------------------------------------
extern "C" void kernel_launch(void* const* d_in, const int* in_sizes, int n_in,
                              void* d_out, int out_size){
    const float* x     = (const float*)d_in[0];
    const float* xw    = (const float*)d_in[1];
    const float* dtw   = (const float*)d_in[2];
    const float* dtb   = (const float*)d_in[3];
    const float* alogs = (const float*)d_in[4];
    const float* Ds    = (const float*)d_in[5];
    const float* lnw   = (const float*)d_in[6];
    const float* lnb   = (const float*)d_in[7];
    float* out = (float*)d_out;

    k_transpose<<<dim3(Ll/32, Dd/32, Bsz), dim3(32,8)>>>(x);
    k_proj     <<<dim3(Ll/128, 2, Bsz), 128>>>(xw, dtw, dtb);
    k_scanA    <<<dim3(NCk, Kk, Bsz), Dd>>>(alogs);
    k_mid      <<<(Bsz*Kk*Dd*Nn + 255)/256, 256>>>();
    k_scanB    <<<dim3(NCk, Kk, Bsz), Dd>>>(alogs, Ds);
    k_merge    <<<Bsz*Ll/8, 256>>>(lnw, lnb, out);
}

// round 4
// speedup vs baseline: 1.1323x; 1.1323x over previous
#include <cuda_runtime.h>
#include <math.h>

#define Bsz 4
#define Dd  96
#define Hh  64
#define Ww  64
#define Ll  4096
#define Kk  4
#define Nn  16
#define Rr  6
#define C38 38
#define NCk 64   // number of chunks
#define LCk 64   // chunk length (NCk*LCk == Ll)

// ---------------- scratch (__device__ globals; no allocations) ----------------
__device__ float g_xpf  [Bsz*Ll*Dd];           // x permuted (B,L,D), row-major spatial
__device__ float g_xpt  [Bsz*Ll*Dd];           // x permuted (B,L,D), col-major spatial
__device__ float g_delta[Bsz*Kk*Ll*Dd];        // softplus(delta) (B,K,L,D)
__device__ float g_Bsc  [Bsz*Kk*Ll*Nn];        // Bs (B,K,L,N)
__device__ float g_Csc  [Bsz*Kk*Ll*Nn];        // Cs (B,K,L,N)
__device__ float g_hc   [Bsz*Kk*NCk*Dd*Nn];    // chunk-local end states
__device__ float g_Pp   [Bsz*Kk*NCk*Dd*Nn];    // chunk decay products
__device__ float g_hin  [Bsz*Kk*NCk*Dd*Nn];    // chunk incoming states
__device__ float g_ys   [Kk*Bsz*Ll*Dd];        // per-direction y in merge-target space

__device__ __forceinline__ float ex2f(float x){
    float r; asm("ex2.approx.ftz.f32 %0, %1;" : "=f"(r) : "f"(x)); return r;
}
__device__ __forceinline__ float softplus_f(float x){
    return fmaxf(x, 0.f) + log1pf(__expf(-fabsf(x)));
}

// ---------------- kernel 1: transpose x -> (B,L,D) in both traversal orders ---
__global__ void k_transpose(const float* __restrict__ x){
    __shared__ float tile[32][33];
    int b = blockIdx.z, d0 = blockIdx.y*32, l0 = blockIdx.x*32;
    int tx = threadIdx.x, ty = threadIdx.y;     // block (32,8)
    #pragma unroll
    for (int i=0;i<4;i++){
        tile[ty+8*i][tx] = x[((long)b*Dd + d0+ty+8*i)*Ll + l0+tx];
    }
    __syncthreads();
    #pragma unroll
    for (int i=0;i<4;i++){
        int l = l0 + ty + 8*i;
        int d = d0 + tx;
        float v = tile[tx][ty+8*i];
        g_xpf[((long)b*Ll + l)*Dd + d] = v;
        int lp = ((l & 63) << 6) | (l >> 6);    // spatial transpose index
        g_xpt[((long)b*Ll + lp)*Dd + d] = v;
    }
}

// ---------------- kernel 2: projections (x_dbl split + dt proj + softplus) ----
__global__ void __launch_bounds__(128) k_proj(const float* __restrict__ xw,
                                              const float* __restrict__ dtw,
                                              const float* __restrict__ dtb){
    __shared__ float swx [2*C38*Dd];
    __shared__ float swdt[2*Dd*Rr];
    __shared__ float sbia[2*Dd];
    int o = blockIdx.y, b = blockIdx.z;
    int tid = threadIdx.x;
    for (int i=tid;i<2*C38*Dd;i+=128){
        int ki = i/(C38*Dd); int rem = i - ki*(C38*Dd);
        swx[i] = xw[(o + 2*ki)*C38*Dd + rem];
    }
    for (int i=tid;i<2*Dd*Rr;i+=128){
        int ki = i/(Dd*Rr); int rem = i - ki*(Dd*Rr);
        swdt[i] = dtw[(o + 2*ki)*Dd*Rr + rem];
    }
    for (int i=tid;i<2*Dd;i+=128){
        int ki = i/Dd; int rem = i - ki*Dd;
        sbia[i] = dtb[(o + 2*ki)*Dd + rem];
    }
    __syncthreads();

    int p = blockIdx.x*128 + tid;
    const float* xp = (o==0 ? g_xpf : g_xpt) + ((long)b*Ll + p)*Dd;
    float xv[Dd];
    #pragma unroll
    for (int i=0;i<Dd/4;i++){
        float4 v = reinterpret_cast<const float4*>(xp)[i];
        xv[4*i]=v.x; xv[4*i+1]=v.y; xv[4*i+2]=v.z; xv[4*i+3]=v.w;
    }

    for (int ki=0; ki<2; ki++){
        int k = o + 2*ki;
        int l = (ki==0) ? p : (Ll-1-p);
        const float* wk = swx + ki*C38*Dd;
        long bkl = ((long)(b*Kk + k))*Ll + l;

        // dts (first R rows)
        float dts[Rr];
        #pragma unroll
        for (int c=0;c<Rr;c++){
            float acc = 0.f;
            #pragma unroll
            for (int d=0; d<Dd; d++) acc += xv[d]*wk[c*Dd+d];
            dts[c] = acc;
        }
        // Bs rows
        for (int cc=0; cc<Nn/4; cc++){
            const float* w0 = wk + (Rr + 4*cc)*Dd;
            float a0=0,a1=0,a2=0,a3=0;
            #pragma unroll
            for (int d=0; d<Dd; d++){
                float xd = xv[d];
                a0 += xd*w0[d]; a1 += xd*w0[Dd+d];
                a2 += xd*w0[2*Dd+d]; a3 += xd*w0[3*Dd+d];
            }
            reinterpret_cast<float4*>(g_Bsc + bkl*Nn)[cc] = make_float4(a0,a1,a2,a3);
        }
        // Cs rows
        for (int cc=0; cc<Nn/4; cc++){
            const float* w0 = wk + (Rr + Nn + 4*cc)*Dd;
            float a0=0,a1=0,a2=0,a3=0;
            #pragma unroll
            for (int d=0; d<Dd; d++){
                float xd = xv[d];
                a0 += xd*w0[d]; a1 += xd*w0[Dd+d];
                a2 += xd*w0[2*Dd+d]; a3 += xd*w0[3*Dd+d];
            }
            reinterpret_cast<float4*>(g_Csc + bkl*Nn)[cc] = make_float4(a0,a1,a2,a3);
        }
        // delta = softplus(dts @ dtW + bias)
        const float* wd  = swdt + ki*Dd*Rr;
        const float* bia = sbia + ki*Dd;
        float* dout = g_delta + bkl*Dd;
        for (int dd=0; dd<Dd; dd+=4){
            float aa[4];
            #pragma unroll
            for (int q=0;q<4;q++){
                float acc = bia[dd+q];
                #pragma unroll
                for (int r=0;r<Rr;r++) acc += dts[r]*wd[(dd+q)*Rr + r];
                aa[q] = softplus_f(acc);
            }
            reinterpret_cast<float4*>(dout + dd)[0] = make_float4(aa[0],aa[1],aa[2],aa[3]);
        }
    }
}

// ---------------- kernel 3: pass A (chunk-local scan, zero init) --------------
__global__ void __launch_bounds__(Dd) k_scanA(const float* __restrict__ A_logs){
    __shared__ float4 sB[LCk*Nn/4];
    int c = blockIdx.x, k = blockIdx.y, b = blockIdx.z;
    int d = threadIdx.x;
    long bk = (long)b*Kk + k;

    const float4* gB4 = reinterpret_cast<const float4*>(g_Bsc + (bk*Ll + (long)c*LCk)*Nn);
    for (int i=d; i<LCk*Nn/4; i+=Dd) sB[i] = gB4[i];
    __syncthreads();

    float A2[Nn];
    const float* al = A_logs + (k*Dd + d)*Nn;
    #pragma unroll
    for (int n=0;n<Nn;n++) A2[n] = -__expf(al[n]) * 1.4426950408889634f;

    float h[Nn];
    #pragma unroll
    for (int n=0;n<Nn;n++) h[n] = 0.f;
    float S = 0.f;

    const float* dptr = g_delta + (bk*Ll + (long)c*LCk)*Dd + d;
    const float* xp = (k & 1) ? g_xpt : g_xpf;
    int l0 = c*LCk;
    const float* uptr; int ustr;
    if (k < 2){ uptr = xp + ((long)b*Ll + l0)*Dd + d;           ustr =  Dd; }
    else      { uptr = xp + ((long)b*Ll + (Ll-1-l0))*Dd + d;    ustr = -Dd; }

    #pragma unroll 2
    for (int j=0;j<LCk;j++){
        float dlt = dptr[j*Dd];
        float u = *uptr; uptr += ustr;
        float du = dlt*u;
        S += dlt;
        const float4* bj = sB + j*(Nn/4);
        #pragma unroll
        for (int q=0;q<Nn/4;q++){
            float4 bb = bj[q];
            h[4*q+0] = h[4*q+0]*ex2f(dlt*A2[4*q+0]) + du*bb.x;
            h[4*q+1] = h[4*q+1]*ex2f(dlt*A2[4*q+1]) + du*bb.y;
            h[4*q+2] = h[4*q+2]*ex2f(dlt*A2[4*q+2]) + du*bb.z;
            h[4*q+3] = h[4*q+3]*ex2f(dlt*A2[4*q+3]) + du*bb.w;
        }
    }
    long base = ((bk*NCk + c)*Dd + d)*Nn;
    float4* hcp = reinterpret_cast<float4*>(g_hc + base);
    float4* Ppp = reinterpret_cast<float4*>(g_Pp + base);
    #pragma unroll
    for (int q=0;q<Nn/4;q++){
        hcp[q] = make_float4(h[4*q], h[4*q+1], h[4*q+2], h[4*q+3]);
        Ppp[q] = make_float4(ex2f(A2[4*q]*S), ex2f(A2[4*q+1]*S),
                             ex2f(A2[4*q+2]*S), ex2f(A2[4*q+3]*S));
    }
}

// ---------------- kernel 4: inter-chunk scan (software-pipelined loads) ------
// Loads of P/hc are independent of the recurrence; batch them 16 chunks at a
// time (32 outstanding coalesced LDGs -> MLP~32) and prefetch the next group
// while scanning the current one. Serial cost: ~4 latency waves + 64 FMAs.
#define MID_G 16
#define MID_NG (NCk/MID_G)
__global__ void __launch_bounds__(256) k_mid(){
    int g = blockIdx.x*blockDim.x + threadIdx.x;   // B*K*D*N threads
    if (g >= Bsz*Kk*Dd*Nn) return;
    const int STR = Dd*Nn;                         // stride between chunks
    long base0 = g + ((long)(g / (Dd*Nn))) * (long)(NCk-1) * STR;
    // base0 = ((bk*NCk + 0)*Dd + d)*Nn + n  ==  bk*NCk*STR + d*Nn + n
    //       = g + bk*(NCk-1)*STR   since g = bk*STR + d*Nn + n

    float P[2][MID_G], Hc[2][MID_G];

    // prefetch group 0
    #pragma unroll
    for (int i=0;i<MID_G;i++){
        long idx = base0 + (long)i*STR;
        P [0][i] = g_Pp[idx];
        Hc[0][i] = g_hc[idx];
    }

    float hin = 0.f;
    #pragma unroll
    for (int grp=0; grp<MID_NG; grp++){
        int cur = grp & 1, nxt = cur ^ 1;
        if (grp+1 < MID_NG){
            #pragma unroll
            for (int i=0;i<MID_G;i++){
                long idx = base0 + (long)((grp+1)*MID_G + i)*STR;
                P [nxt][i] = g_Pp[idx];
                Hc[nxt][i] = g_hc[idx];
            }
        }
        #pragma unroll
        for (int i=0;i<MID_G;i++){
            long idx = base0 + (long)(grp*MID_G + i)*STR;
            g_hin[idx] = hin;
            hin = hin*P[cur][i] + Hc[cur][i];
        }
    }
}

// ---------------- kernel 5: pass B (replay with correct h_in, emit y) --------
__global__ void __launch_bounds__(Dd) k_scanB(const float* __restrict__ A_logs,
                                              const float* __restrict__ Ds){
    __shared__ float4 sB[LCk*Nn/4];
    __shared__ float4 sC[LCk*Nn/4];
    int c = blockIdx.x, k = blockIdx.y, b = blockIdx.z;
    int d = threadIdx.x;
    long bk = (long)b*Kk + k;

    const float4* gB4 = reinterpret_cast<const float4*>(g_Bsc + (bk*Ll + (long)c*LCk)*Nn);
    const float4* gC4 = reinterpret_cast<const float4*>(g_Csc + (bk*Ll + (long)c*LCk)*Nn);
    for (int i=d; i<LCk*Nn/4; i+=Dd){ sB[i] = gB4[i]; sC[i] = gC4[i]; }
    __syncthreads();

    float A2[Nn];
    const float* al = A_logs + (k*Dd + d)*Nn;
    #pragma unroll
    for (int n=0;n<Nn;n++) A2[n] = -__expf(al[n]) * 1.4426950408889634f;

    float h[Nn];
    long base = ((bk*NCk + c)*Dd + d)*Nn;
    #pragma unroll
    for (int q=0;q<Nn/4;q++){
        float4 v = reinterpret_cast<const float4*>(g_hin + base)[q];
        h[4*q]=v.x; h[4*q+1]=v.y; h[4*q+2]=v.z; h[4*q+3]=v.w;
    }
    float Dskip = Ds[k*Dd + d];

    const float* dptr = g_delta + (bk*Ll + (long)c*LCk)*Dd + d;
    const float* xp = (k & 1) ? g_xpt : g_xpf;
    int l0 = c*LCk;
    const float* uptr; int ustr;
    if (k < 2){ uptr = xp + ((long)b*Ll + l0)*Dd + d;        ustr =  Dd; }
    else      { uptr = xp + ((long)b*Ll + (Ll-1-l0))*Dd + d; ustr = -Dd; }

    float* yout = g_ys + ((long)k*Bsz + b)*Ll*Dd + d;

    #pragma unroll 2
    for (int j=0;j<LCk;j++){
        float dlt = dptr[j*Dd];
        float u = *uptr; uptr += ustr;
        float du = dlt*u;
        float y = Dskip*u;
        const float4* bj = sB + j*(Nn/4);
        const float4* cj = sC + j*(Nn/4);
        #pragma unroll
        for (int q=0;q<Nn/4;q++){
            float4 bb = bj[q];
            float4 cc = cj[q];
            h[4*q+0] = h[4*q+0]*ex2f(dlt*A2[4*q+0]) + du*bb.x;  y += h[4*q+0]*cc.x;
            h[4*q+1] = h[4*q+1]*ex2f(dlt*A2[4*q+1]) + du*bb.y;  y += h[4*q+1]*cc.y;
            h[4*q+2] = h[4*q+2]*ex2f(dlt*A2[4*q+2]) + du*bb.z;  y += h[4*q+2]*cc.z;
            h[4*q+3] = h[4*q+3]*ex2f(dlt*A2[4*q+3]) + du*bb.w;  y += h[4*q+3]*cc.w;
        }
        int l = l0 + j;
        int t;
        if (k == 0)      t = l;
        else if (k == 1) t = ((l & 63) << 6) | (l >> 6);
        else if (k == 2) t = Ll-1-l;
        else { int q2 = Ll-1-l; t = ((q2 & 63) << 6) | (q2 >> 6); }
        yout[(long)t*Dd] = y;
    }
}

// ---------------- kernel 6: 4-way merge + LayerNorm --------------------------
__global__ void __launch_bounds__(256) k_merge(const float* __restrict__ lnw,
                                               const float* __restrict__ lnb,
                                               float* __restrict__ out){
    const long BLD = (long)Bsz*Ll*Dd;
    int warp = threadIdx.x >> 5, lane = threadIdx.x & 31;
    int pos = blockIdx.x*8 + warp;
    int b = pos >> 12;              // Ll = 4096
    int l = pos & (Ll-1);
    long base = ((long)b*Ll + l)*Dd;
    float s[3]; float sum = 0.f, sq = 0.f;
    #pragma unroll
    for (int i=0;i<3;i++){
        long off = base + lane + 32*i;
        float v = g_ys[off] + g_ys[off + BLD] + g_ys[off + 2*BLD] + g_ys[off + 3*BLD];
        s[i] = v; sum += v; sq += v*v;
    }
    #pragma unroll
    for (int o2=16;o2>0;o2>>=1){
        sum += __shfl_xor_sync(0xffffffffu, sum, o2);
        sq  += __shfl_xor_sync(0xffffffffu, sq,  o2);
    }
    float mean = sum * (1.f/Dd);
    float var  = sq  * (1.f/Dd) - mean*mean;
    float inv  = rsqrtf(var + 1e-5f);
    #pragma unroll
    for (int i=0;i<3;i++){
        int dch = lane + 32*i;
        out[base + dch] = (s[i]-mean)*inv*lnw[dch] + lnb[dch];
    }
}

// ---------------- launch ------------------------------------------------------
extern "C" void kernel_launch(void* const* d_in, const int* in_sizes, int n_in,
                              void* d_out, int out_size){
    const float* x     = (const float*)d_in[0];
    const float* xw    = (const float*)d_in[1];
    const float* dtw   = (const float*)d_in[2];
    const float* dtb   = (const float*)d_in[3];
    const float* alogs = (const float*)d_in[4];
    const float* Ds    = (const float*)d_in[5];
    const float* lnw   = (const float*)d_in[6];
    const float* lnb   = (const float*)d_in[7];
    float* out = (float*)d_out;

    k_transpose<<<dim3(Ll/32, Dd/32, Bsz), dim3(32,8)>>>(x);
    k_proj     <<<dim3(Ll/128, 2, Bsz), 128>>>(xw, dtw, dtb);
    k_scanA    <<<dim3(NCk, Kk, Bsz), Dd>>>(alogs);
    k_mid      <<<(Bsz*Kk*Dd*Nn + 255)/256, 256>>>();
    k_scanB    <<<dim3(NCk, Kk, Bsz), Dd>>>(alogs, Ds);
    k_merge    <<<Bsz*Ll/8, 256>>>(lnw, lnb, out);
}